// round 1
// baseline (speedup 1.0000x reference)
#include <cuda_runtime.h>
#include <math.h>

#define BB   2
#define SS   2048
#define DM   768
#define NH   12
#define DK   64
#define BHT  (BB*NH)      // 24
#define MTOT (BB*SS)      // 4096

// ---------------- scratch (device globals: no allocations allowed) ----------
__device__ float g_qh[BHT * SS * DK];      // [b*H+h][s][d]
__device__ float g_kh[BHT * SS * DK];
__device__ float g_vh[BHT * SS * DK];
__device__ float g_concat[BB * SS * DM];   // [b][s][h*64+d]

// ---------------------------------------------------------------------------
// Y[M,768] = X[M,768] @ W[768,768]^T + bias
// Both X and W are K-contiguous (row-major with K inner) -> symmetric tiling.
// Tile 64x64, BK=32, 256 threads, 4x4 micro-tile per thread.
// Smem stored k-outer so the inner loop is 2x LDS.128 per 16 FFMA,
// conflict-free (one broadcast + one 16-consecutive-float4 access).
// HEAD_OUT: scatter to [b*H+h][s][d] layout (N-tile width 64 == Dk, so each
// x-block maps to exactly one head; stores stay float4-coalesced).
// ---------------------------------------------------------------------------
template <bool HEAD_OUT>
__global__ __launch_bounds__(256)
void sgemm_nt(const float* __restrict__ X,
              const float* __restrict__ W,
              const float* __restrict__ bias,
              float* __restrict__ Y)
{
    constexpr int BK = 32;
    __shared__ float Xs[BK][64];   // [k][m]
    __shared__ float Ws[BK][64];   // [k][n]

    const int tid = threadIdx.x;
    const int tx  = tid & 15;      // n group
    const int ty  = tid >> 4;      // m group
    const int m0  = blockIdx.y * 64;
    const int n0  = blockIdx.x * 64;

    float acc[4][4] = {};

    for (int k0 = 0; k0 < DM; k0 += BK) {
        // load + transpose tiles: 64 rows x 32 k = 512 float4, 2 per thread
        #pragma unroll
        for (int r = 0; r < 2; r++) {
            int i   = tid + 256 * r;       // float4 index 0..511
            int row = i >> 3;              // 8 float4 per row
            int c4  = (i & 7) << 2;        // k offset within tile
            float4 xv = *reinterpret_cast<const float4*>(&X[(m0 + row) * DM + k0 + c4]);
            Xs[c4 + 0][row] = xv.x; Xs[c4 + 1][row] = xv.y;
            Xs[c4 + 2][row] = xv.z; Xs[c4 + 3][row] = xv.w;
            float4 wv = *reinterpret_cast<const float4*>(&W[(n0 + row) * DM + k0 + c4]);
            Ws[c4 + 0][row] = wv.x; Ws[c4 + 1][row] = wv.y;
            Ws[c4 + 2][row] = wv.z; Ws[c4 + 3][row] = wv.w;
        }
        __syncthreads();

        #pragma unroll
        for (int k = 0; k < BK; k++) {
            float4 a4 = *reinterpret_cast<const float4*>(&Xs[k][ty * 4]);
            float4 b4 = *reinterpret_cast<const float4*>(&Ws[k][tx * 4]);
            float av[4] = {a4.x, a4.y, a4.z, a4.w};
            float bv[4] = {b4.x, b4.y, b4.z, b4.w};
            #pragma unroll
            for (int i = 0; i < 4; i++)
                #pragma unroll
                for (int j = 0; j < 4; j++)
                    acc[i][j] += av[i] * bv[j];
        }
        __syncthreads();
    }

    // epilogue: bias + store
    float bv[4];
    #pragma unroll
    for (int j = 0; j < 4; j++) bv[j] = bias[n0 + tx * 4 + j];

    #pragma unroll
    for (int i = 0; i < 4; i++) {
        int m = m0 + ty * 4 + i;
        float4 o;
        o.x = acc[i][0] + bv[0];
        o.y = acc[i][1] + bv[1];
        o.z = acc[i][2] + bv[2];
        o.w = acc[i][3] + bv[3];
        if (HEAD_OUT) {
            int b = m >> 11;               // m / 2048
            int s = m & (SS - 1);
            int h = n0 >> 6;               // head index (tile width == 64)
            float* dst = &Y[(((b * NH + h) * SS) + s) * DK + tx * 4];
            *reinterpret_cast<float4*>(dst) = o;
        } else {
            *reinterpret_cast<float4*>(&Y[m * DM + n0 + tx * 4]) = o;
        }
    }
}

// ---------------------------------------------------------------------------
// fp32 flash attention. One block per (bh, 64-query-row tile).
// 256 threads, 4x4 micro-tiles for both S = Q@K^T and O += P@V.
// Online softmax; width-16 shuffle reductions (the 16 threads sharing a row
// group are contiguous lanes).
// ---------------------------------------------------------------------------
__global__ __launch_bounds__(256)
void flash_attn(const float* __restrict__ Qh,
                const float* __restrict__ Kh,
                const float* __restrict__ Vh,
                float* __restrict__ Out)
{
    __shared__ float Qs[DK][64];   // [d][row]   (transposed)
    __shared__ float Ks[DK][64];   // [d][col]   (transposed)
    __shared__ float Vs[64][DK];   // [kv][d]    (natural)
    __shared__ float Ps[64][64];   // [row][kv]

    const int tid = threadIdx.x;
    const int tx  = tid & 15;      // col / d group
    const int ty  = tid >> 4;      // row group
    const int bh  = blockIdx.y;    // 0..23
    const int q0  = blockIdx.x * 64;

    const float* Qb = Qh + (size_t)bh * SS * DK;
    const float* Kb = Kh + (size_t)bh * SS * DK;
    const float* Vb = Vh + (size_t)bh * SS * DK;

    // load Q tile transposed: 64 rows x 64 d = 1024 float4, 4 per thread
    #pragma unroll
    for (int r = 0; r < 4; r++) {
        int i   = tid + 256 * r;
        int row = i >> 4;              // 16 float4 per row
        int d4  = (i & 15) << 2;
        float4 v = *reinterpret_cast<const float4*>(&Qb[(q0 + row) * DK + d4]);
        Qs[d4 + 0][row] = v.x; Qs[d4 + 1][row] = v.y;
        Qs[d4 + 2][row] = v.z; Qs[d4 + 3][row] = v.w;
    }

    float m_i[4], l_i[4], o[4][4];
    #pragma unroll
    for (int i = 0; i < 4; i++) {
        m_i[i] = -INFINITY;
        l_i[i] = 0.0f;
        #pragma unroll
        for (int j = 0; j < 4; j++) o[i][j] = 0.0f;
    }

    const float scale = 0.125f;    // 1/sqrt(Dk)

    for (int kv0 = 0; kv0 < SS; kv0 += 64) {
        __syncthreads();   // previous iteration's readers done (and Qs visible on iter 0)

        // load K (transposed) + V (natural) tiles
        #pragma unroll
        for (int r = 0; r < 4; r++) {
            int i   = tid + 256 * r;
            int row = i >> 4;
            int d4  = (i & 15) << 2;
            float4 kv = *reinterpret_cast<const float4*>(&Kb[(kv0 + row) * DK + d4]);
            Ks[d4 + 0][row] = kv.x; Ks[d4 + 1][row] = kv.y;
            Ks[d4 + 2][row] = kv.z; Ks[d4 + 3][row] = kv.w;
            float4 vv = *reinterpret_cast<const float4*>(&Vb[(kv0 + row) * DK + d4]);
            *reinterpret_cast<float4*>(&Vs[row][d4]) = vv;
        }
        __syncthreads();

        // S = Q @ K^T  (4x4 per thread over 64 d)
        float sacc[4][4] = {};
        #pragma unroll 16
        for (int d = 0; d < DK; d++) {
            float4 a4 = *reinterpret_cast<const float4*>(&Qs[d][ty * 4]);
            float4 b4 = *reinterpret_cast<const float4*>(&Ks[d][tx * 4]);
            float av[4] = {a4.x, a4.y, a4.z, a4.w};
            float bvv[4] = {b4.x, b4.y, b4.z, b4.w};
            #pragma unroll
            for (int i = 0; i < 4; i++)
                #pragma unroll
                for (int j = 0; j < 4; j++)
                    sacc[i][j] += av[i] * bvv[j];
        }

        // online softmax (per row: max, rescale, exp, sum)
        #pragma unroll
        for (int i = 0; i < 4; i++) {
            float mx = -INFINITY;
            #pragma unroll
            for (int j = 0; j < 4; j++) {
                sacc[i][j] *= scale;
                mx = fmaxf(mx, sacc[i][j]);
            }
            #pragma unroll
            for (int off = 8; off >= 1; off >>= 1)
                mx = fmaxf(mx, __shfl_xor_sync(0xffffffffu, mx, off, 16));

            float mn    = fmaxf(m_i[i], mx);
            float alpha = __expf(m_i[i] - mn);   // 0 on first tile (m_i = -inf)
            m_i[i] = mn;

            float rs = 0.0f;
            #pragma unroll
            for (int j = 0; j < 4; j++) {
                float p = __expf(sacc[i][j] - mn);
                sacc[i][j] = p;
                rs += p;
            }
            #pragma unroll
            for (int off = 8; off >= 1; off >>= 1)
                rs += __shfl_xor_sync(0xffffffffu, rs, off, 16);

            l_i[i] = l_i[i] * alpha + rs;
            #pragma unroll
            for (int j = 0; j < 4; j++) o[i][j] *= alpha;
        }

        // stage P to smem (row-major, float4 stores, conflict-free)
        #pragma unroll
        for (int i = 0; i < 4; i++) {
            float4 p4;
            p4.x = sacc[i][0]; p4.y = sacc[i][1];
            p4.z = sacc[i][2]; p4.w = sacc[i][3];
            *reinterpret_cast<float4*>(&Ps[ty * 4 + i][tx * 4]) = p4;
        }
        __syncthreads();

        // O += P @ V   (kv unrolled by 4: 8 LDS.128 per 64 FFMA)
        #pragma unroll 4
        for (int kv = 0; kv < 64; kv += 4) {
            float p[4][4], vv[4][4];
            #pragma unroll
            for (int i = 0; i < 4; i++) {
                float4 p4 = *reinterpret_cast<const float4*>(&Ps[ty * 4 + i][kv]);
                p[i][0] = p4.x; p[i][1] = p4.y; p[i][2] = p4.z; p[i][3] = p4.w;
            }
            #pragma unroll
            for (int t = 0; t < 4; t++) {
                float4 v4 = *reinterpret_cast<const float4*>(&Vs[kv + t][tx * 4]);
                vv[t][0] = v4.x; vv[t][1] = v4.y; vv[t][2] = v4.z; vv[t][3] = v4.w;
            }
            #pragma unroll
            for (int i = 0; i < 4; i++)
                #pragma unroll
                for (int j = 0; j < 4; j++) {
                    o[i][j] += p[i][0] * vv[0][j];
                    o[i][j] += p[i][1] * vv[1][j];
                    o[i][j] += p[i][2] * vv[2][j];
                    o[i][j] += p[i][3] * vv[3][j];
                }
        }
    }

    // normalize + write to concat layout [b][s][h*64+d]
    const int b = bh / NH;
    const int h = bh % NH;
    #pragma unroll
    for (int i = 0; i < 4; i++) {
        float inv = 1.0f / l_i[i];
        int srow  = q0 + ty * 4 + i;
        float4 ov;
        ov.x = o[i][0] * inv; ov.y = o[i][1] * inv;
        ov.z = o[i][2] * inv; ov.w = o[i][3] * inv;
        *reinterpret_cast<float4*>(
            &Out[((size_t)(b * SS + srow)) * DM + h * DK + tx * 4]) = ov;
    }
}

// ---------------------------------------------------------------------------
extern "C" void kernel_launch(void* const* d_in, const int* in_sizes, int n_in,
                              void* d_out, int out_size)
{
    const float* q  = (const float*)d_in[0];
    const float* k  = (const float*)d_in[1];
    const float* v  = (const float*)d_in[2];
    const float* Wk = (const float*)d_in[3];
    const float* bk = (const float*)d_in[4];
    const float* Wo = (const float*)d_in[5];
    const float* bo = (const float*)d_in[6];
    float* out = (float*)d_out;

    float *qh, *kh, *vh, *concat;
    cudaGetSymbolAddress((void**)&qh,     g_qh);
    cudaGetSymbolAddress((void**)&kh,     g_kh);
    cudaGetSymbolAddress((void**)&vh,     g_vh);
    cudaGetSymbolAddress((void**)&concat, g_concat);

    dim3 gemm_grid(DM / 64, MTOT / 64);     // (12, 64)
    dim3 attn_grid(SS / 64, BHT);           // (32, 24)

    // 3 projections (all through Wk/bk -- faithful to the reference bug)
    sgemm_nt<true><<<gemm_grid, 256>>>(q, Wk, bk, qh);
    sgemm_nt<true><<<gemm_grid, 256>>>(k, Wk, bk, kh);
    sgemm_nt<true><<<gemm_grid, 256>>>(v, Wk, bk, vh);

    // attention
    flash_attn<<<attn_grid, 256>>>(qh, kh, vh, concat);

    // output projection
    sgemm_nt<false><<<gemm_grid, 256>>>(concat, Wo, bo, out);
}

// round 3
// speedup vs baseline: 1.4379x; 1.4379x over previous
#include <cuda_runtime.h>
#include <cuda_bf16.h>
#include <math.h>
#include <stdint.h>

#define BB   2
#define SS   2048
#define DM   768
#define NH   12
#define DK   64
#define BHT  (BB*NH)      // 24
#define MTOT (BB*SS)      // 4096

// ---------------- scratch (device globals: no allocations allowed) ----------
__device__ float g_qh[BHT * SS * DK];      // [b*H+h][s][d]
__device__ float g_kh[BHT * SS * DK];
__device__ float g_vh[BHT * SS * DK];
__device__ float g_concat[BB * SS * DM];   // [b][s][h*64+d]

// ============================= helpers =====================================
__device__ __forceinline__ uint32_t smem_u32(const void* p) {
    uint32_t a;
    asm("{ .reg .u64 t; cvta.to.shared.u64 t, %1; cvt.u32.u64 %0, t; }"
        : "=r"(a) : "l"(p));
    return a;
}

__device__ __forceinline__ void ldsm_x4(uint32_t* r, uint32_t addr) {
    asm volatile("ldmatrix.sync.aligned.m8n8.x4.shared.b16 {%0,%1,%2,%3}, [%4];"
                 : "=r"(r[0]), "=r"(r[1]), "=r"(r[2]), "=r"(r[3]) : "r"(addr));
}

// D = A(16x16 bf16, row) @ B(16x8 bf16, col) + C, fp32 accum
__device__ __forceinline__ void mma_bf16(float* d, const uint32_t* a,
                                         const uint32_t* b) {
    asm volatile(
        "mma.sync.aligned.m16n8k16.row.col.f32.bf16.bf16.f32 "
        "{%0,%1,%2,%3}, {%4,%5,%6,%7}, {%8,%9}, {%0,%1,%2,%3};"
        : "+f"(d[0]), "+f"(d[1]), "+f"(d[2]), "+f"(d[3])
        : "r"(a[0]), "r"(a[1]), "r"(a[2]), "r"(a[3]),
          "r"(b[0]), "r"(b[1]));
}

__device__ __forceinline__ uint32_t pack_bf16_hi(float x, float y) {
    __nv_bfloat162 h = __floats2bfloat162_rn(x, y);
    return *reinterpret_cast<uint32_t*>(&h);
}

// ---------------------------------------------------------------------------
// HMMA GEMM: Y[M,768] = X[M,768] @ W[768,768]^T + bias, bf16 3-term hi/lo
// split for fp32-grade accuracy. CTA 128x128, 8 warps (2x4), warp 64x32,
// BK=32. Smem padded to 40 halves/row -> conflict-free ldmatrix.
// HEAD_OUT: scatter to [b*H+h][s][d].
// ---------------------------------------------------------------------------
#define PADK 40

template <bool HEAD_OUT>
__global__ __launch_bounds__(256)
void gemm_mma(const float* __restrict__ X,
              const float* __restrict__ W,
              const float* __restrict__ bias,
              float* __restrict__ Y)
{
    __shared__ __nv_bfloat16 AH[128][PADK];
    __shared__ __nv_bfloat16 AL[128][PADK];
    __shared__ __nv_bfloat16 BHs[128][PADK];
    __shared__ __nv_bfloat16 BLs[128][PADK];

    const int tid = threadIdx.x;
    const int wid = tid >> 5;
    const int lid = tid & 31;
    const int m0  = blockIdx.y * 128;
    const int n0  = blockIdx.x * 128;
    const int wm  = (wid >> 2) * 64;   // warp M offset in tile
    const int wn  = (wid & 3) * 32;    // warp N offset in tile

    float acc[4][4][4];
    #pragma unroll
    for (int i = 0; i < 4; i++)
        #pragma unroll
        for (int j = 0; j < 4; j++)
            #pragma unroll
            for (int t = 0; t < 4; t++) acc[i][j][t] = 0.0f;

    for (int k0 = 0; k0 < DM; k0 += 32) {
        // ---- load fp32, split to bf16 hi/lo, store to smem ----
        #pragma unroll
        for (int r = 0; r < 4; r++) {
            int i   = tid + 256 * r;     // float4 slot 0..1023
            int row = i >> 3;            // 8 float4 per row
            int c4  = (i & 7) << 2;      // col (halves == floats)

            float4 xv = *reinterpret_cast<const float4*>(&X[(size_t)(m0 + row) * DM + k0 + c4]);
            uint32_t h0 = pack_bf16_hi(xv.x, xv.y);
            uint32_t h1 = pack_bf16_hi(xv.z, xv.w);
            float rx = xv.x - __bfloat162float(__ushort_as_bfloat16((uint16_t)h0));
            float ry = xv.y - __bfloat162float(__ushort_as_bfloat16((uint16_t)(h0 >> 16)));
            float rz = xv.z - __bfloat162float(__ushort_as_bfloat16((uint16_t)h1));
            float rw = xv.w - __bfloat162float(__ushort_as_bfloat16((uint16_t)(h1 >> 16)));
            *reinterpret_cast<uint32_t*>(&AH[row][c4])     = h0;
            *reinterpret_cast<uint32_t*>(&AH[row][c4 + 2]) = h1;
            *reinterpret_cast<uint32_t*>(&AL[row][c4])     = pack_bf16_hi(rx, ry);
            *reinterpret_cast<uint32_t*>(&AL[row][c4 + 2]) = pack_bf16_hi(rz, rw);

            float4 wv = *reinterpret_cast<const float4*>(&W[(size_t)(n0 + row) * DM + k0 + c4]);
            uint32_t g0 = pack_bf16_hi(wv.x, wv.y);
            uint32_t g1 = pack_bf16_hi(wv.z, wv.w);
            float sx = wv.x - __bfloat162float(__ushort_as_bfloat16((uint16_t)g0));
            float sy = wv.y - __bfloat162float(__ushort_as_bfloat16((uint16_t)(g0 >> 16)));
            float sz = wv.z - __bfloat162float(__ushort_as_bfloat16((uint16_t)g1));
            float sw = wv.w - __bfloat162float(__ushort_as_bfloat16((uint16_t)(g1 >> 16)));
            *reinterpret_cast<uint32_t*>(&BHs[row][c4])     = g0;
            *reinterpret_cast<uint32_t*>(&BHs[row][c4 + 2]) = g1;
            *reinterpret_cast<uint32_t*>(&BLs[row][c4])     = pack_bf16_hi(sx, sy);
            *reinterpret_cast<uint32_t*>(&BLs[row][c4 + 2]) = pack_bf16_hi(sz, sw);
        }
        __syncthreads();

        // ---- MMA over 2 k-steps of 16 ----
        #pragma unroll
        for (int kk = 0; kk < 2; kk++) {
            const int kc = kk * 16;

            uint32_t ah[4][4], al[4][4];
            {
                int arow = wm + (lid & 15);
                int acol = kc + (lid >> 4) * 8;
                #pragma unroll
                for (int i = 0; i < 4; i++) {
                    ldsm_x4(ah[i], smem_u32(&AH[arow + i * 16][acol]));
                    ldsm_x4(al[i], smem_u32(&AL[arow + i * 16][acol]));
                }
            }
            uint32_t bh[2][4], bl[2][4];
            {
                int brow = wn + (lid & 7) + (lid >> 4) * 8;
                int bcol = kc + ((lid >> 3) & 1) * 8;
                #pragma unroll
                for (int p = 0; p < 2; p++) {
                    ldsm_x4(bh[p], smem_u32(&BHs[brow + p * 16][bcol]));
                    ldsm_x4(bl[p], smem_u32(&BLs[brow + p * 16][bcol]));
                }
            }

            #pragma unroll
            for (int i = 0; i < 4; i++)
                #pragma unroll
                for (int j = 0; j < 4; j++) {
                    const uint32_t* bhj = &bh[j >> 1][(j & 1) * 2];
                    const uint32_t* blj = &bl[j >> 1][(j & 1) * 2];
                    mma_bf16(acc[i][j], ah[i], bhj);   // hi*hi
                    mma_bf16(acc[i][j], ah[i], blj);   // hi*lo
                    mma_bf16(acc[i][j], al[i], bhj);   // lo*hi
                }
        }
        __syncthreads();
    }

    // ---- epilogue: bias + store (fragment layout: rows r,r+8; cols c,c+1) ----
    const int fr = lid >> 2;
    const int fc = (lid & 3) * 2;
    #pragma unroll
    for (int j = 0; j < 4; j++) {
        const int n = n0 + wn + j * 8 + fc;
        const float b0 = bias[n];
        const float b1 = bias[n + 1];
        #pragma unroll
        for (int i = 0; i < 4; i++) {
            #pragma unroll
            for (int half = 0; half < 2; half++) {
                const int m = m0 + wm + i * 16 + fr + half * 8;
                float2 val;
                val.x = acc[i][j][half * 2 + 0] + b0;
                val.y = acc[i][j][half * 2 + 1] + b1;
                if (HEAD_OUT) {
                    const int b  = m >> 11;
                    const int s  = m & (SS - 1);
                    const int h  = n >> 6;
                    const int dk = n & 63;
                    *reinterpret_cast<float2*>(
                        &Y[(((size_t)(b * NH + h) * SS) + s) * DK + dk]) = val;
                } else {
                    *reinterpret_cast<float2*>(&Y[(size_t)m * DM + n]) = val;
                }
            }
        }
    }
}

// ---------------------------------------------------------------------------
// fp32 flash attention (unchanged — at fp32 FMA/crossbar roofline)
// ---------------------------------------------------------------------------
__global__ __launch_bounds__(256)
void flash_attn(const float* __restrict__ Qh,
                const float* __restrict__ Kh,
                const float* __restrict__ Vh,
                float* __restrict__ Out)
{
    __shared__ float Qs[DK][64];
    __shared__ float Ks[DK][64];
    __shared__ float Vs[64][DK];
    __shared__ float Ps[64][64];

    const int tid = threadIdx.x;
    const int tx  = tid & 15;
    const int ty  = tid >> 4;
    const int bh  = blockIdx.y;
    const int q0  = blockIdx.x * 64;

    const float* Qb = Qh + (size_t)bh * SS * DK;
    const float* Kb = Kh + (size_t)bh * SS * DK;
    const float* Vb = Vh + (size_t)bh * SS * DK;

    #pragma unroll
    for (int r = 0; r < 4; r++) {
        int i   = tid + 256 * r;
        int row = i >> 4;
        int d4  = (i & 15) << 2;
        float4 v = *reinterpret_cast<const float4*>(&Qb[(q0 + row) * DK + d4]);
        Qs[d4 + 0][row] = v.x; Qs[d4 + 1][row] = v.y;
        Qs[d4 + 2][row] = v.z; Qs[d4 + 3][row] = v.w;
    }

    float m_i[4], l_i[4], o[4][4];
    #pragma unroll
    for (int i = 0; i < 4; i++) {
        m_i[i] = -INFINITY;
        l_i[i] = 0.0f;
        #pragma unroll
        for (int j = 0; j < 4; j++) o[i][j] = 0.0f;
    }

    const float scale = 0.125f;

    for (int kv0 = 0; kv0 < SS; kv0 += 64) {
        __syncthreads();

        #pragma unroll
        for (int r = 0; r < 4; r++) {
            int i   = tid + 256 * r;
            int row = i >> 4;
            int d4  = (i & 15) << 2;
            float4 kv = *reinterpret_cast<const float4*>(&Kb[(kv0 + row) * DK + d4]);
            Ks[d4 + 0][row] = kv.x; Ks[d4 + 1][row] = kv.y;
            Ks[d4 + 2][row] = kv.z; Ks[d4 + 3][row] = kv.w;
            float4 vv = *reinterpret_cast<const float4*>(&Vb[(kv0 + row) * DK + d4]);
            *reinterpret_cast<float4*>(&Vs[row][d4]) = vv;
        }
        __syncthreads();

        float sacc[4][4] = {};
        #pragma unroll 16
        for (int d = 0; d < DK; d++) {
            float4 a4 = *reinterpret_cast<const float4*>(&Qs[d][ty * 4]);
            float4 b4 = *reinterpret_cast<const float4*>(&Ks[d][tx * 4]);
            float av[4] = {a4.x, a4.y, a4.z, a4.w};
            float bvv[4] = {b4.x, b4.y, b4.z, b4.w};
            #pragma unroll
            for (int i = 0; i < 4; i++)
                #pragma unroll
                for (int j = 0; j < 4; j++)
                    sacc[i][j] += av[i] * bvv[j];
        }

        #pragma unroll
        for (int i = 0; i < 4; i++) {
            float mx = -INFINITY;
            #pragma unroll
            for (int j = 0; j < 4; j++) {
                sacc[i][j] *= scale;
                mx = fmaxf(mx, sacc[i][j]);
            }
            #pragma unroll
            for (int off = 8; off >= 1; off >>= 1)
                mx = fmaxf(mx, __shfl_xor_sync(0xffffffffu, mx, off, 16));

            float mn    = fmaxf(m_i[i], mx);
            float alpha = __expf(m_i[i] - mn);
            m_i[i] = mn;

            float rs = 0.0f;
            #pragma unroll
            for (int j = 0; j < 4; j++) {
                float p = __expf(sacc[i][j] - mn);
                sacc[i][j] = p;
                rs += p;
            }
            #pragma unroll
            for (int off = 8; off >= 1; off >>= 1)
                rs += __shfl_xor_sync(0xffffffffu, rs, off, 16);

            l_i[i] = l_i[i] * alpha + rs;
            #pragma unroll
            for (int j = 0; j < 4; j++) o[i][j] *= alpha;
        }

        #pragma unroll
        for (int i = 0; i < 4; i++) {
            float4 p4;
            p4.x = sacc[i][0]; p4.y = sacc[i][1];
            p4.z = sacc[i][2]; p4.w = sacc[i][3];
            *reinterpret_cast<float4*>(&Ps[ty * 4 + i][tx * 4]) = p4;
        }
        __syncthreads();

        #pragma unroll 4
        for (int kv = 0; kv < 64; kv += 4) {
            float p[4][4], vv[4][4];
            #pragma unroll
            for (int i = 0; i < 4; i++) {
                float4 p4 = *reinterpret_cast<const float4*>(&Ps[ty * 4 + i][kv]);
                p[i][0] = p4.x; p[i][1] = p4.y; p[i][2] = p4.z; p[i][3] = p4.w;
            }
            #pragma unroll
            for (int t = 0; t < 4; t++) {
                float4 v4 = *reinterpret_cast<const float4*>(&Vs[kv + t][tx * 4]);
                vv[t][0] = v4.x; vv[t][1] = v4.y; vv[t][2] = v4.z; vv[t][3] = v4.w;
            }
            #pragma unroll
            for (int i = 0; i < 4; i++)
                #pragma unroll
                for (int j = 0; j < 4; j++) {
                    o[i][j] += p[i][0] * vv[0][j];
                    o[i][j] += p[i][1] * vv[1][j];
                    o[i][j] += p[i][2] * vv[2][j];
                    o[i][j] += p[i][3] * vv[3][j];
                }
        }
    }

    const int b = bh / NH;
    const int h = bh % NH;
    #pragma unroll
    for (int i = 0; i < 4; i++) {
        float inv = 1.0f / l_i[i];
        int srow  = q0 + ty * 4 + i;
        float4 ov;
        ov.x = o[i][0] * inv; ov.y = o[i][1] * inv;
        ov.z = o[i][2] * inv; ov.w = o[i][3] * inv;
        *reinterpret_cast<float4*>(
            &Out[((size_t)(b * SS + srow)) * DM + h * DK + tx * 4]) = ov;
    }
}

// ---------------------------------------------------------------------------
extern "C" void kernel_launch(void* const* d_in, const int* in_sizes, int n_in,
                              void* d_out, int out_size)
{
    const float* q  = (const float*)d_in[0];
    const float* k  = (const float*)d_in[1];
    const float* v  = (const float*)d_in[2];
    const float* Wk = (const float*)d_in[3];
    const float* bk = (const float*)d_in[4];
    const float* Wo = (const float*)d_in[5];
    const float* bo = (const float*)d_in[6];
    float* out = (float*)d_out;

    float *qh, *kh, *vh, *concat;
    cudaGetSymbolAddress((void**)&qh,     g_qh);
    cudaGetSymbolAddress((void**)&kh,     g_kh);
    cudaGetSymbolAddress((void**)&vh,     g_vh);
    cudaGetSymbolAddress((void**)&concat, g_concat);

    dim3 gemm_grid(DM / 128, MTOT / 128);   // (6, 32)
    dim3 attn_grid(SS / 64, BHT);           // (32, 24)

    // 3 projections (all through Wk/bk -- faithful to the reference bug)
    gemm_mma<true><<<gemm_grid, 256>>>(q, Wk, bk, qh);
    gemm_mma<true><<<gemm_grid, 256>>>(k, Wk, bk, kh);
    gemm_mma<true><<<gemm_grid, 256>>>(v, Wk, bk, vh);

    // attention (fp32)
    flash_attn<<<attn_grid, 256>>>(qh, kh, vh, concat);

    // output projection
    gemm_mma<false><<<gemm_grid, 256>>>(concat, Wo, bo, out);
}

// round 5
// speedup vs baseline: 2.9977x; 2.0848x over previous
#include <cuda_runtime.h>
#include <cuda_bf16.h>
#include <math.h>
#include <stdint.h>

#define BB   2
#define SS   2048
#define DM   768
#define NH   12
#define DK   64
#define BHT  (BB*NH)      // 24
#define MTOT (BB*SS)      // 4096

// ---------------- scratch (device globals: no allocations allowed) ----------
__device__ float g_qh[BHT * SS * DK];      // [b*H+h][s][d]
__device__ float g_kh[BHT * SS * DK];
__device__ float g_vh[BHT * SS * DK];
__device__ float g_concat[BB * SS * DM];   // [b][s][h*64+d]

// ============================= helpers =====================================
__device__ __forceinline__ uint32_t smem_u32(const void* p) {
    uint32_t a;
    asm("{ .reg .u64 t; cvta.to.shared.u64 t, %1; cvt.u32.u64 %0, t; }"
        : "=r"(a) : "l"(p));
    return a;
}

__device__ __forceinline__ void ldsm_x4(uint32_t* r, uint32_t addr) {
    asm volatile("ldmatrix.sync.aligned.m8n8.x4.shared.b16 {%0,%1,%2,%3}, [%4];"
                 : "=r"(r[0]), "=r"(r[1]), "=r"(r[2]), "=r"(r[3]) : "r"(addr));
}
__device__ __forceinline__ void ldsm_x4_t(uint32_t* r, uint32_t addr) {
    asm volatile("ldmatrix.sync.aligned.m8n8.x4.trans.shared.b16 {%0,%1,%2,%3}, [%4];"
                 : "=r"(r[0]), "=r"(r[1]), "=r"(r[2]), "=r"(r[3]) : "r"(addr));
}

// D = A(16x16 bf16, row) @ B(16x8 bf16, col) + C, fp32 accum
__device__ __forceinline__ void mma_bf16(float* d, const uint32_t* a,
                                         const uint32_t* b) {
    asm volatile(
        "mma.sync.aligned.m16n8k16.row.col.f32.bf16.bf16.f32 "
        "{%0,%1,%2,%3}, {%4,%5,%6,%7}, {%8,%9}, {%0,%1,%2,%3};"
        : "+f"(d[0]), "+f"(d[1]), "+f"(d[2]), "+f"(d[3])
        : "r"(a[0]), "r"(a[1]), "r"(a[2]), "r"(a[3]),
          "r"(b[0]), "r"(b[1]));
}

__device__ __forceinline__ uint32_t pack_bf16_hi(float x, float y) {
    __nv_bfloat162 h = __floats2bfloat162_rn(x, y);
    return *reinterpret_cast<uint32_t*>(&h);
}
__device__ __forceinline__ void split2(float x, float y, uint32_t& hi, uint32_t& lo) {
    uint32_t h = pack_bf16_hi(x, y);
    float hx = __bfloat162float(__ushort_as_bfloat16((uint16_t)h));
    float hy = __bfloat162float(__ushort_as_bfloat16((uint16_t)(h >> 16)));
    hi = h;
    lo = pack_bf16_hi(x - hx, y - hy);
}

// ---------------------------------------------------------------------------
// HMMA GEMM: Y[M,768] = X[M,768] @ W[768,768]^T + bias, bf16 3-term hi/lo
// split. CTA 128x128, 8 warps (2x4), warp 64x32, BK=32.
// ---------------------------------------------------------------------------
#define PADK 40

template <bool HEAD_OUT>
__global__ __launch_bounds__(256)
void gemm_mma(const float* __restrict__ X,
              const float* __restrict__ W,
              const float* __restrict__ bias,
              float* __restrict__ Y)
{
    __shared__ __nv_bfloat16 AH[128][PADK];
    __shared__ __nv_bfloat16 AL[128][PADK];
    __shared__ __nv_bfloat16 BHs[128][PADK];
    __shared__ __nv_bfloat16 BLs[128][PADK];

    const int tid = threadIdx.x;
    const int wid = tid >> 5;
    const int lid = tid & 31;
    const int m0  = blockIdx.y * 128;
    const int n0  = blockIdx.x * 128;
    const int wm  = (wid >> 2) * 64;
    const int wn  = (wid & 3) * 32;

    float acc[4][4][4];
    #pragma unroll
    for (int i = 0; i < 4; i++)
        #pragma unroll
        for (int j = 0; j < 4; j++)
            #pragma unroll
            for (int t = 0; t < 4; t++) acc[i][j][t] = 0.0f;

    for (int k0 = 0; k0 < DM; k0 += 32) {
        #pragma unroll
        for (int r = 0; r < 4; r++) {
            int i   = tid + 256 * r;
            int row = i >> 3;
            int c4  = (i & 7) << 2;

            float4 xv = *reinterpret_cast<const float4*>(&X[(size_t)(m0 + row) * DM + k0 + c4]);
            uint32_t h0, l0, h1, l1;
            split2(xv.x, xv.y, h0, l0);
            split2(xv.z, xv.w, h1, l1);
            *reinterpret_cast<uint32_t*>(&AH[row][c4])     = h0;
            *reinterpret_cast<uint32_t*>(&AH[row][c4 + 2]) = h1;
            *reinterpret_cast<uint32_t*>(&AL[row][c4])     = l0;
            *reinterpret_cast<uint32_t*>(&AL[row][c4 + 2]) = l1;

            float4 wv = *reinterpret_cast<const float4*>(&W[(size_t)(n0 + row) * DM + k0 + c4]);
            split2(wv.x, wv.y, h0, l0);
            split2(wv.z, wv.w, h1, l1);
            *reinterpret_cast<uint32_t*>(&BHs[row][c4])     = h0;
            *reinterpret_cast<uint32_t*>(&BHs[row][c4 + 2]) = h1;
            *reinterpret_cast<uint32_t*>(&BLs[row][c4])     = l0;
            *reinterpret_cast<uint32_t*>(&BLs[row][c4 + 2]) = l1;
        }
        __syncthreads();

        #pragma unroll
        for (int kk = 0; kk < 2; kk++) {
            const int kc = kk * 16;

            uint32_t ah[4][4], al[4][4];
            {
                int arow = wm + (lid & 15);
                int acol = kc + (lid >> 4) * 8;
                #pragma unroll
                for (int i = 0; i < 4; i++) {
                    ldsm_x4(ah[i], smem_u32(&AH[arow + i * 16][acol]));
                    ldsm_x4(al[i], smem_u32(&AL[arow + i * 16][acol]));
                }
            }
            uint32_t bh[2][4], bl[2][4];
            {
                int brow = wn + (lid & 7) + (lid >> 4) * 8;
                int bcol = kc + ((lid >> 3) & 1) * 8;
                #pragma unroll
                for (int p = 0; p < 2; p++) {
                    ldsm_x4(bh[p], smem_u32(&BHs[brow + p * 16][bcol]));
                    ldsm_x4(bl[p], smem_u32(&BLs[brow + p * 16][bcol]));
                }
            }

            #pragma unroll
            for (int i = 0; i < 4; i++)
                #pragma unroll
                for (int j = 0; j < 4; j++) {
                    const uint32_t* bhj = &bh[j >> 1][(j & 1) * 2];
                    const uint32_t* blj = &bl[j >> 1][(j & 1) * 2];
                    mma_bf16(acc[i][j], ah[i], bhj);
                    mma_bf16(acc[i][j], ah[i], blj);
                    mma_bf16(acc[i][j], al[i], bhj);
                }
        }
        __syncthreads();
    }

    const int fr = lid >> 2;
    const int fc = (lid & 3) * 2;
    #pragma unroll
    for (int j = 0; j < 4; j++) {
        const int n = n0 + wn + j * 8 + fc;
        const float b0 = bias[n];
        const float b1 = bias[n + 1];
        #pragma unroll
        for (int i = 0; i < 4; i++) {
            #pragma unroll
            for (int half = 0; half < 2; half++) {
                const int m = m0 + wm + i * 16 + fr + half * 8;
                float2 val;
                val.x = acc[i][j][half * 2 + 0] + b0;
                val.y = acc[i][j][half * 2 + 1] + b1;
                if (HEAD_OUT) {
                    const int b  = m >> 11;
                    const int s  = m & (SS - 1);
                    const int h  = n >> 6;
                    const int dk = n & 63;
                    *reinterpret_cast<float2*>(
                        &Y[(((size_t)(b * NH + h) * SS) + s) * DK + dk]) = val;
                } else {
                    *reinterpret_cast<float2*>(&Y[(size_t)m * DM + n]) = val;
                }
            }
        }
    }
}

// ---------------------------------------------------------------------------
// HMMA flash attention. CTA = (bh, 128 q-rows), 8 warps, warp = 16 q-rows.
// bf16 3-term hi/lo split on BOTH gemms (Q@K^T and P@V). fp32 softmax on
// fragments; row stats per 4-lane shuffle group. Q smem reused for K/V.
// ---------------------------------------------------------------------------
#define PADH 72   // halves per smem row (144B stride -> conflict-free ldmatrix)

__global__ __launch_bounds__(256)
void flash_mma(const float* __restrict__ Qg,
               const float* __restrict__ Kg,
               const float* __restrict__ Vg,
               float* __restrict__ Out)
{
    __shared__ __align__(16) char raw[2 * 128 * PADH * 2];   // 36864 B

    __nv_bfloat16 (*Qh_s)[PADH] = reinterpret_cast<__nv_bfloat16(*)[PADH]>(raw);
    __nv_bfloat16 (*Ql_s)[PADH] = reinterpret_cast<__nv_bfloat16(*)[PADH]>(raw + 18432);
    __nv_bfloat16 (*Kh_s)[PADH] = reinterpret_cast<__nv_bfloat16(*)[PADH]>(raw);
    __nv_bfloat16 (*Kl_s)[PADH] = reinterpret_cast<__nv_bfloat16(*)[PADH]>(raw + 9216);
    __nv_bfloat16 (*Vh_s)[PADH] = reinterpret_cast<__nv_bfloat16(*)[PADH]>(raw + 18432);
    __nv_bfloat16 (*Vl_s)[PADH] = reinterpret_cast<__nv_bfloat16(*)[PADH]>(raw + 27648);

    const int tid = threadIdx.x;
    const int wid = tid >> 5;
    const int lid = tid & 31;
    const int bh  = blockIdx.y;
    const int q0  = blockIdx.x * 128;

    const float* Qb = Qg + (size_t)bh * SS * DK;
    const float* Kb = Kg + (size_t)bh * SS * DK;
    const float* Vb = Vg + (size_t)bh * SS * DK;

    // ---- prologue: load + split Q tile (128x64) into smem ----
    #pragma unroll
    for (int r = 0; r < 8; r++) {
        int i   = tid + 256 * r;
        int row = i >> 4;
        int c4  = (i & 15) << 2;
        float4 v = *reinterpret_cast<const float4*>(&Qb[(q0 + row) * DK + c4]);
        uint32_t h0, l0, h1, l1;
        split2(v.x, v.y, h0, l0);
        split2(v.z, v.w, h1, l1);
        *reinterpret_cast<uint32_t*>(&Qh_s[row][c4])     = h0;
        *reinterpret_cast<uint32_t*>(&Qh_s[row][c4 + 2]) = h1;
        *reinterpret_cast<uint32_t*>(&Ql_s[row][c4])     = l0;
        *reinterpret_cast<uint32_t*>(&Ql_s[row][c4 + 2]) = l1;
    }
    __syncthreads();

    // ---- hoist Q A-fragments (4 k-steps, hi + lo) into registers ----
    uint32_t qfh[4][4], qfl[4][4];
    {
        int arow = wid * 16 + (lid & 15);
        int acol = (lid >> 4) * 8;
        #pragma unroll
        for (int ks = 0; ks < 4; ks++) {
            ldsm_x4(qfh[ks], smem_u32(&Qh_s[arow][ks * 16 + acol]));
            ldsm_x4(qfl[ks], smem_u32(&Ql_s[arow][ks * 16 + acol]));
        }
    }

    float m_i[2], l_i[2], oacc[8][4];
    #pragma unroll
    for (int h2 = 0; h2 < 2; h2++) { m_i[h2] = -INFINITY; l_i[h2] = 0.0f; }
    #pragma unroll
    for (int j = 0; j < 8; j++)
        #pragma unroll
        for (int t = 0; t < 4; t++) oacc[j][t] = 0.0f;

    const float scale = 0.125f;   // 1/sqrt(Dk)

    for (int kv0 = 0; kv0 < SS; kv0 += 64) {
        __syncthreads();

        // ---- load + split K,V tiles (64x64 each) ----
        #pragma unroll
        for (int r = 0; r < 4; r++) {
            int i   = tid + 256 * r;
            int row = i >> 4;
            int c4  = (i & 15) << 2;
            float4 kv = *reinterpret_cast<const float4*>(&Kb[(kv0 + row) * DK + c4]);
            uint32_t h0, l0, h1, l1;
            split2(kv.x, kv.y, h0, l0);
            split2(kv.z, kv.w, h1, l1);
            *reinterpret_cast<uint32_t*>(&Kh_s[row][c4])     = h0;
            *reinterpret_cast<uint32_t*>(&Kh_s[row][c4 + 2]) = h1;
            *reinterpret_cast<uint32_t*>(&Kl_s[row][c4])     = l0;
            *reinterpret_cast<uint32_t*>(&Kl_s[row][c4 + 2]) = l1;

            float4 vv = *reinterpret_cast<const float4*>(&Vb[(kv0 + row) * DK + c4]);
            split2(vv.x, vv.y, h0, l0);
            split2(vv.z, vv.w, h1, l1);
            *reinterpret_cast<uint32_t*>(&Vh_s[row][c4])     = h0;
            *reinterpret_cast<uint32_t*>(&Vh_s[row][c4 + 2]) = h1;
            *reinterpret_cast<uint32_t*>(&Vl_s[row][c4])     = l0;
            *reinterpret_cast<uint32_t*>(&Vl_s[row][c4 + 2]) = l1;
        }
        __syncthreads();

        // ---- S = Q @ K^T (16 x 64 per warp) ----
        float sacc[8][4];
        #pragma unroll
        for (int j = 0; j < 8; j++)
            #pragma unroll
            for (int t = 0; t < 4; t++) sacc[j][t] = 0.0f;

        #pragma unroll
        for (int ks = 0; ks < 4; ks++) {
            #pragma unroll
            for (int jj = 0; jj < 4; jj++) {
                int brow = jj * 16 + (lid & 7) + ((lid >> 4) << 3);
                int bcol = ks * 16 + ((lid >> 3) & 1) * 8;
                uint32_t kb_h[4], kb_l[4];
                ldsm_x4(kb_h, smem_u32(&Kh_s[brow][bcol]));
                ldsm_x4(kb_l, smem_u32(&Kl_s[brow][bcol]));
                #pragma unroll
                for (int p = 0; p < 2; p++) {
                    float* d = sacc[jj * 2 + p];
                    mma_bf16(d, qfh[ks], &kb_h[p * 2]);
                    mma_bf16(d, qfh[ks], &kb_l[p * 2]);
                    mma_bf16(d, qfl[ks], &kb_h[p * 2]);
                }
            }
        }

        // ---- online softmax ----
        #pragma unroll
        for (int h2 = 0; h2 < 2; h2++) {
            const int base = h2 * 2;
            float mx = -INFINITY;
            #pragma unroll
            for (int j = 0; j < 8; j++) {
                sacc[j][base]     *= scale;
                sacc[j][base + 1] *= scale;
                mx = fmaxf(mx, fmaxf(sacc[j][base], sacc[j][base + 1]));
            }
            mx = fmaxf(mx, __shfl_xor_sync(0xffffffffu, mx, 1));
            mx = fmaxf(mx, __shfl_xor_sync(0xffffffffu, mx, 2));

            float mn    = fmaxf(m_i[h2], mx);
            float alpha = __expf(m_i[h2] - mn);
            m_i[h2] = mn;

            float rs = 0.0f;
            #pragma unroll
            for (int j = 0; j < 8; j++) {
                float p0 = __expf(sacc[j][base]     - mn);
                float p1 = __expf(sacc[j][base + 1] - mn);
                sacc[j][base]     = p0;
                sacc[j][base + 1] = p1;
                rs += p0 + p1;
            }
            rs += __shfl_xor_sync(0xffffffffu, rs, 1);
            rs += __shfl_xor_sync(0xffffffffu, rs, 2);

            l_i[h2] = l_i[h2] * alpha + rs;
            #pragma unroll
            for (int j = 0; j < 8; j++) {
                oacc[j][base]     *= alpha;
                oacc[j][base + 1] *= alpha;
            }
        }

        // ---- O += P @ V (P regs -> bf16 split; V^T frags via ldmatrix.trans)
        #pragma unroll
        for (int t = 0; t < 4; t++) {
            uint32_t pah[4], pal[4];
            split2(sacc[2 * t][0],     sacc[2 * t][1],     pah[0], pal[0]);
            split2(sacc[2 * t][2],     sacc[2 * t][3],     pah[1], pal[1]);
            split2(sacc[2 * t + 1][0], sacc[2 * t + 1][1], pah[2], pal[2]);
            split2(sacc[2 * t + 1][2], sacc[2 * t + 1][3], pah[3], pal[3]);

            const int vrow  = t * 16 + (lid & 15);
            const int vcolw = (lid >> 4) << 3;
            #pragma unroll
            for (int dd = 0; dd < 4; dd++) {         // d-col groups of 16
                uint32_t vh4[4], vl4[4];
                ldsm_x4_t(vh4, smem_u32(&Vh_s[vrow][dd * 16 + vcolw]));
                ldsm_x4_t(vl4, smem_u32(&Vl_s[vrow][dd * 16 + vcolw]));
                float* d0 = oacc[dd * 2 + 0];
                float* d1 = oacc[dd * 2 + 1];
                mma_bf16(d0, pah, &vh4[0]);
                mma_bf16(d0, pal, &vh4[0]);
                mma_bf16(d0, pah, &vl4[0]);
                mma_bf16(d1, pah, &vh4[2]);
                mma_bf16(d1, pal, &vh4[2]);
                mma_bf16(d1, pah, &vl4[2]);
            }
        }
    }

    // ---- epilogue: normalize + write concat [b][s][h*64+d] ----
    const int b    = bh / NH;
    const int head = bh % NH;
    const int fr   = lid >> 2;
    const int fc   = (lid & 3) * 2;
    #pragma unroll
    for (int h2 = 0; h2 < 2; h2++) {
        const float inv = 1.0f / l_i[h2];
        const int srow  = q0 + wid * 16 + fr + 8 * h2;
        float* orow = &Out[((size_t)(b * SS + srow)) * DM + head * DK];
        #pragma unroll
        for (int j = 0; j < 8; j++) {
            float2 val;
            val.x = oacc[j][h2 * 2 + 0] * inv;
            val.y = oacc[j][h2 * 2 + 1] * inv;
            *reinterpret_cast<float2*>(&orow[j * 8 + fc]) = val;
        }
    }
}

// ---------------------------------------------------------------------------
extern "C" void kernel_launch(void* const* d_in, const int* in_sizes, int n_in,
                              void* d_out, int out_size)
{
    const float* q  = (const float*)d_in[0];
    const float* k  = (const float*)d_in[1];
    const float* v  = (const float*)d_in[2];
    const float* Wk = (const float*)d_in[3];
    const float* bk = (const float*)d_in[4];
    const float* Wo = (const float*)d_in[5];
    const float* bo = (const float*)d_in[6];
    float* out = (float*)d_out;

    float *qh, *kh, *vh, *concat;
    cudaGetSymbolAddress((void**)&qh,     g_qh);
    cudaGetSymbolAddress((void**)&kh,     g_kh);
    cudaGetSymbolAddress((void**)&vh,     g_vh);
    cudaGetSymbolAddress((void**)&concat, g_concat);

    dim3 gemm_grid(DM / 128, MTOT / 128);   // (6, 32)
    dim3 attn_grid(SS / 128, BHT);          // (16, 24)

    // 3 projections (all through Wk/bk -- faithful to the reference bug)
    gemm_mma<true><<<gemm_grid, 256>>>(q, Wk, bk, qh);
    gemm_mma<true><<<gemm_grid, 256>>>(k, Wk, bk, kh);
    gemm_mma<true><<<gemm_grid, 256>>>(v, Wk, bk, vh);

    // attention (HMMA bf16 split)
    flash_mma<<<attn_grid, 256>>>(qh, kh, vh, concat);

    // output projection
    gemm_mma<false><<<gemm_grid, 256>>>(concat, Wo, bo, out);
}